// round 16
// baseline (speedup 1.0000x reference)
#include <cuda_runtime.h>
#include <cuda_fp16.h>
#include <cstdint>

#define BATCH 4
#define S_LEN 4096
#define D_MODEL 1024

// ---------------- scratch (module-load device globals) ----------------
__device__ __half g_eh[(size_t)BATCH * S_LEN * S_LEN];                  // fp16 exp(logits)
__device__ float  g_rowsum[(size_t)BATCH * S_LEN];                      // fp32 row sums
__device__ __half g_qkvh[(size_t)BATCH * S_LEN * 3 * D_MODEL];          // fp16 [B,S,3D]
__device__ __half g_xh[(size_t)BATCH * S_LEN * D_MODEL];                // fp16 x
__device__ __half g_wqkvh[(size_t)3 * D_MODEL * D_MODEL];               // fp16 W_qkv
__device__ __half g_woh[(size_t)D_MODEL * D_MODEL];                     // fp16 W_o
__device__ __half g_attnh[(size_t)BATCH * S_LEN * D_MODEL];             // fp16 attn

// ---------------- helpers ----------------
__device__ __forceinline__ uint32_t smem_u32(const void* p) {
    uint32_t a;
    asm("{ .reg .u64 t; cvta.to.shared.u64 t, %1; cvt.u32.u64 %0, t; }" : "=r"(a) : "l"(p));
    return a;
}
__device__ __forceinline__ void cp16(uint32_t dst, const void* src) {
    asm volatile("cp.async.cg.shared.global [%0], [%1], 16;" :: "r"(dst), "l"(src));
}
__device__ __forceinline__ void ldsm_x4(uint32_t* r, uint32_t addr) {
    asm volatile("ldmatrix.sync.aligned.m8n8.x4.shared.b16 {%0,%1,%2,%3}, [%4];"
                 : "=r"(r[0]), "=r"(r[1]), "=r"(r[2]), "=r"(r[3]) : "r"(addr));
}
__device__ __forceinline__ void ldsm_x4_t(uint32_t* r, uint32_t addr) {
    asm volatile("ldmatrix.sync.aligned.m8n8.x4.trans.shared.b16 {%0,%1,%2,%3}, [%4];"
                 : "=r"(r[0]), "=r"(r[1]), "=r"(r[2]), "=r"(r[3]) : "r"(addr));
}
__device__ __forceinline__ void mma16816(float* c,
                                         uint32_t a0, uint32_t a1, uint32_t a2, uint32_t a3,
                                         uint32_t b0, uint32_t b1) {
    asm volatile(
        "mma.sync.aligned.m16n8k16.row.col.f32.f16.f16.f32 "
        "{%0,%1,%2,%3}, {%4,%5,%6,%7}, {%8,%9}, {%0,%1,%2,%3};"
        : "+f"(c[0]), "+f"(c[1]), "+f"(c[2]), "+f"(c[3])
        : "r"(a0), "r"(a1), "r"(a2), "r"(a3), "r"(b0), "r"(b1));
}

// ---------------- fp16 GEMM ----------------
// BT=true : C[M,N] = f(A[M,K] @ B[N,K]^T)   (NT, both K-major)
// BT=false: C[M,N] = f(A[M,K] @ B[K,N])     (NN, B row-major [K,N], ldmatrix.trans)
// MODE: 0 = fp32 C (*alpha), 1 = fp16 C (*alpha),
//       2 = fp16 C = exp(acc*alpha) + fp32 rowsum atomics, 3 = fp16 C = acc / rowsum[row].
#define TM 128
#define TN 128
#define TBK 64
#define A_BYTES (TM * TBK * 2)            // 16384
#define STAGE_BYTES ((TM + TN) * TBK * 2) // 32768
#define NSTAGE 3
#define SMEM_TOTAL (NSTAGE * STAGE_BYTES) // 98304

template<int MODE, bool BT>
__global__ void __launch_bounds__(256, 2)
gemm_f16(const __half* __restrict__ A, const __half* __restrict__ B, void* __restrict__ Cv,
         int Kd, int lda, int ldb, int ldc,
         size_t sA, size_t sB, size_t sC, float alpha, float* __restrict__ rs)
{
    extern __shared__ char smem[];
    const uint32_t sb = smem_u32(smem);
    const int tid  = threadIdx.x;
    const int warp = tid >> 5, lane = tid & 31;
    const int wm = (warp & 3) * 32;       // 4 warps along M
    const int wn = (warp >> 2) * 64;      // 2 warps along N

    const int cta_m = blockIdx.y * TM;
    const int cta_n = blockIdx.x * TN;
    const __half* Ab = A + sA * blockIdx.z + (size_t)cta_m * lda;
    const __half* Bb = BT ? (B + sB * blockIdx.z + (size_t)cta_n * ldb)
                          : (B + sB * blockIdx.z + cta_n);

    // ---- cp.async loader geometry ----
    const int ld_row = tid >> 3;          // A: 0..31 (stepped by +32)
    const int ld_s   = tid & 7;
    const uint32_t ld_sw = (uint32_t)((ld_s ^ (ld_row & 7)) << 4);

    const char* a_src[4];
    uint32_t a_dst[4];
    #pragma unroll
    for (int p = 0; p < 4; p++) {
        int r = ld_row + p * 32;
        a_src[p] = (const char*)(Ab + (size_t)r * lda) + ld_s * 16;
        a_dst[p] = (uint32_t)(r * 128) + ld_sw;
    }

    const char* b_src[4];
    uint32_t b_dst[4];
    if (BT) {
        #pragma unroll
        for (int p = 0; p < 4; p++) {
            int r = ld_row + p * 32;
            b_src[p] = (const char*)(Bb + (size_t)r * ldb) + ld_s * 16;
            b_dst[p] = (uint32_t)(r * 128) + ld_sw + A_BYTES;
        }
    } else {
        // B tile [64 k-rows x 128 n] = 256B/row, 16 chunks; c' = c ^ (r&7)
        const int rr = tid >> 4;          // 0..15 (stepped by +16)
        const int cc = tid & 15;
        #pragma unroll
        for (int p = 0; p < 4; p++) {
            int r = rr + p * 16;
            b_src[p] = (const char*)Bb + (size_t)r * ldb * 2 + cc * 16;
            b_dst[p] = (uint32_t)(r * 256 + ((cc ^ (r & 7)) << 4)) + A_BYTES;
        }
    }

    auto load_stage = [&](uint32_t stoff, int kt) {
        const uint32_t base = sb + stoff;
        const size_t koff_a = (size_t)kt * TBK * 2;
        const size_t koff_b = BT ? koff_a : (size_t)kt * TBK * ldb * 2;
        #pragma unroll
        for (int p = 0; p < 4; p++) cp16(base + a_dst[p], a_src[p] + koff_a);
        #pragma unroll
        for (int p = 0; p < 4; p++) cp16(base + b_dst[p], b_src[p] + koff_b);
        asm volatile("cp.async.commit_group;" ::: "memory");
    };

    float acc[2][8][4];
    #pragma unroll
    for (int i = 0; i < 2; i++)
        #pragma unroll
        for (int j = 0; j < 8; j++)
            #pragma unroll
            for (int k = 0; k < 4; k++) acc[i][j][k] = 0.f;

    const int KT = Kd / TBK;
    load_stage(0, 0);
    if (KT > 1) load_stage(STAGE_BYTES, 1);
    else        asm volatile("cp.async.commit_group;" ::: "memory");

    // ---- fragment-load geometry ----
    const int l15 = lane & 15, l7 = lane & 7, lhi = lane >> 4;
    uint32_t swk[4];
    #pragma unroll
    for (int ks = 0; ks < 4; ks++) swk[ks] = (uint32_t)(((ks * 2 + lhi) ^ l7) << 4);
    const uint32_t arow_off = (uint32_t)((wm + l15) * 128);
    const uint32_t brow_off = (uint32_t)((wn + l15) * 128) + A_BYTES;
    // NN B path (ldmatrix.trans): lane row = kgrp*8 + (l&7); chunk = nseg ^ (l&7)
    const int bn0 = wn >> 3;
    const uint32_t bt_row = (uint32_t)(((lhi & 1) * 8 + l7) * 256) + A_BYTES;
    uint32_t bt_chunk[4];
    #pragma unroll
    for (int j = 0; j < 4; j++)
        bt_chunk[j] = (uint32_t)(((bn0 + 2 * j + ((lane >> 3) & 1)) ^ l7) << 4);

    uint32_t cur_off = 0;
    uint32_t pre_off = 2 * STAGE_BYTES;

    for (int kt = 0; kt < KT; kt++) {
        asm volatile("cp.async.wait_group 1;" ::: "memory");
        __syncthreads();
        if (kt + 2 < KT) load_stage(pre_off, kt + 2);

        const uint32_t arow = sb + cur_off + arow_off;

        uint32_t af[2][2][4], bf[2][4][4];
        // preload ks=0 fragments
        #pragma unroll
        for (int mt = 0; mt < 2; mt++) ldsm_x4(af[0][mt], arow + mt * 2048 + swk[0]);
        if (BT) {
            const uint32_t brow = sb + cur_off + brow_off;
            #pragma unroll
            for (int j = 0; j < 4; j++) ldsm_x4(bf[0][j], brow + j * 2048 + swk[0]);
        } else {
            const uint32_t bbase = sb + cur_off + bt_row;
            #pragma unroll
            for (int j = 0; j < 4; j++) ldsm_x4_t(bf[0][j], bbase + bt_chunk[j]);
        }

        #pragma unroll
        for (int ks = 0; ks < 4; ks++) {
            const int c = ks & 1, n = c ^ 1;
            if (ks < 3) {
                #pragma unroll
                for (int mt = 0; mt < 2; mt++) ldsm_x4(af[n][mt], arow + mt * 2048 + swk[ks + 1]);
                if (BT) {
                    const uint32_t brow = sb + cur_off + brow_off;
                    #pragma unroll
                    for (int j = 0; j < 4; j++) ldsm_x4(bf[n][j], brow + j * 2048 + swk[ks + 1]);
                } else {
                    const uint32_t bbase = sb + cur_off + bt_row + (uint32_t)(ks + 1) * 4096;
                    #pragma unroll
                    for (int j = 0; j < 4; j++) ldsm_x4_t(bf[n][j], bbase + bt_chunk[j]);
                }
            }
            #pragma unroll
            for (int mt = 0; mt < 2; mt++)
                #pragma unroll
                for (int nt = 0; nt < 8; nt++)
                    mma16816(acc[mt][nt],
                             af[c][mt][0], af[c][mt][1], af[c][mt][2], af[c][mt][3],
                             bf[c][nt >> 1][nt & 1], bf[c][nt >> 1][(nt & 1) + 2]);
        }

        uint32_t t = cur_off;
        cur_off = (cur_off == 2 * STAGE_BYTES) ? 0u : cur_off + STAGE_BYTES;
        pre_off = t;
    }

    // ---------------- epilogue ----------------
    const int er = lane >> 2, ec = (lane & 3) * 2;

    if (MODE == 2) {
        __half* C = (__half*)Cv + sC * blockIdx.z;
        float* rsb = rs + (size_t)blockIdx.z * S_LEN + cta_m;
        #pragma unroll
        for (int mt = 0; mt < 2; mt++) {
            const int r0 = wm + mt * 16 + er;
            float s0 = 0.f, s1 = 0.f;
            #pragma unroll
            for (int nt = 0; nt < 8; nt++) {
                const int col = cta_n + wn + nt * 8 + ec;
                float e0 = __expf(acc[mt][nt][0] * alpha);
                float e1 = __expf(acc[mt][nt][1] * alpha);
                float e2 = __expf(acc[mt][nt][2] * alpha);
                float e3 = __expf(acc[mt][nt][3] * alpha);
                s0 += e0 + e1;
                s1 += e2 + e3;
                *(__half2*)&C[(size_t)(cta_m + r0) * ldc + col]     = __floats2half2_rn(e0, e1);
                *(__half2*)&C[(size_t)(cta_m + r0 + 8) * ldc + col] = __floats2half2_rn(e2, e3);
            }
            s0 += __shfl_xor_sync(0xffffffffu, s0, 1);
            s0 += __shfl_xor_sync(0xffffffffu, s0, 2);
            s1 += __shfl_xor_sync(0xffffffffu, s1, 1);
            s1 += __shfl_xor_sync(0xffffffffu, s1, 2);
            if ((lane & 3) == 0) {
                atomicAdd(&rsb[r0],     s0);
                atomicAdd(&rsb[r0 + 8], s1);
            }
        }
    } else if (MODE == 3) {
        __half* C = (__half*)Cv + sC * blockIdx.z;
        const float* rsb = rs + (size_t)blockIdx.z * S_LEN + cta_m;
        #pragma unroll
        for (int mt = 0; mt < 2; mt++) {
            const int r0 = wm + mt * 16 + er;
            const float inv0 = 1.0f / rsb[r0];
            const float inv1 = 1.0f / rsb[r0 + 8];
            #pragma unroll
            for (int nt = 0; nt < 8; nt++) {
                const int col = cta_n + wn + nt * 8 + ec;
                *(__half2*)&C[(size_t)(cta_m + r0) * ldc + col] =
                    __floats2half2_rn(acc[mt][nt][0] * inv0, acc[mt][nt][1] * inv0);
                *(__half2*)&C[(size_t)(cta_m + r0 + 8) * ldc + col] =
                    __floats2half2_rn(acc[mt][nt][2] * inv1, acc[mt][nt][3] * inv1);
            }
        }
    } else {
        #pragma unroll
        for (int mt = 0; mt < 2; mt++) {
            const int row0 = cta_m + wm + mt * 16 + er;
            #pragma unroll
            for (int nt = 0; nt < 8; nt++) {
                const int col = cta_n + wn + nt * 8 + ec;
                if (MODE == 1) {
                    __half* C = (__half*)Cv + sC * blockIdx.z;
                    *(__half2*)&C[(size_t)row0 * ldc + col] =
                        __floats2half2_rn(acc[mt][nt][0] * alpha, acc[mt][nt][1] * alpha);
                    *(__half2*)&C[(size_t)(row0 + 8) * ldc + col] =
                        __floats2half2_rn(acc[mt][nt][2] * alpha, acc[mt][nt][3] * alpha);
                } else {
                    float* C = (float*)Cv + sC * blockIdx.z;
                    *(float2*)&C[(size_t)row0 * ldc + col] =
                        make_float2(acc[mt][nt][0] * alpha, acc[mt][nt][1] * alpha);
                    *(float2*)&C[(size_t)(row0 + 8) * ldc + col] =
                        make_float2(acc[mt][nt][2] * alpha, acc[mt][nt][3] * alpha);
                }
            }
        }
    }
}

// ---------------- prep: all fp32->fp16 converts + rowsum zero, one launch --------
__global__ void prep(const float* __restrict__ x, const float* __restrict__ wq,
                     const float* __restrict__ wo,
                     __half* __restrict__ xh, __half* __restrict__ wqh,
                     __half* __restrict__ woh, float* __restrict__ rowsum,
                     int nx, int nq, int no)
{
    int i = blockIdx.x * blockDim.x + threadIdx.x;
    if (i < (BATCH * S_LEN) / 4)
        ((float4*)rowsum)[i] = make_float4(0.f, 0.f, 0.f, 0.f);

    const float* src; __half* dst; int j = i;
    if (j < nx)            { src = x;  dst = xh;  }
    else { j -= nx;
        if (j < nq)        { src = wq; dst = wqh; }
        else { j -= nq;
            if (j >= no) return;
            src = wo; dst = woh;
        }
    }
    float4 v = ((const float4*)src)[j];
    __half2 h0 = __floats2half2_rn(v.x, v.y);
    __half2 h1 = __floats2half2_rn(v.z, v.w);
    ((uint2*)dst)[j] = make_uint2(*(uint32_t*)&h0, *(uint32_t*)&h1);
}

// ---------------- launch ----------------
extern "C" void kernel_launch(void* const* d_in, const int* in_sizes, int n_in,
                              void* d_out, int out_size)
{
    const float* x    = (const float*)d_in[0];
    const float* wqkv = (const float*)d_in[1];
    const float* wo   = (const float*)d_in[2];
    float* out        = (float*)d_out;

    __half *eh, *qkvh, *xh, *wqkvh, *woh, *attnh;
    float* rowsum;
    cudaGetSymbolAddress((void**)&eh,     g_eh);
    cudaGetSymbolAddress((void**)&rowsum, g_rowsum);
    cudaGetSymbolAddress((void**)&qkvh,   g_qkvh);
    cudaGetSymbolAddress((void**)&xh,     g_xh);
    cudaGetSymbolAddress((void**)&wqkvh,  g_wqkvh);
    cudaGetSymbolAddress((void**)&woh,    g_woh);
    cudaGetSymbolAddress((void**)&attnh,  g_attnh);

    cudaFuncSetAttribute((const void*)gemm_f16<0, true>,  cudaFuncAttributeMaxDynamicSharedMemorySize, SMEM_TOTAL);
    cudaFuncSetAttribute((const void*)gemm_f16<1, true>,  cudaFuncAttributeMaxDynamicSharedMemorySize, SMEM_TOTAL);
    cudaFuncSetAttribute((const void*)gemm_f16<2, true>,  cudaFuncAttributeMaxDynamicSharedMemorySize, SMEM_TOTAL);
    cudaFuncSetAttribute((const void*)gemm_f16<3, false>, cudaFuncAttributeMaxDynamicSharedMemorySize, SMEM_TOTAL);

    const int BS = BATCH * S_LEN;                      // 16384
    const size_t qkv_bs = (size_t)S_LEN * 3 * D_MODEL;
    const size_t log_bs = (size_t)S_LEN * S_LEN;
    const size_t att_bs = (size_t)S_LEN * D_MODEL;

    // 0) converts + rowsum zero in one launch
    {
        int nx = BS * D_MODEL / 4;
        int nq = 3 * D_MODEL * D_MODEL / 4;
        int no = D_MODEL * D_MODEL / 4;
        prep<<<(nx + nq + no + 255) / 256, 256>>>(x, wqkv, wo, xh, wqkvh, woh, rowsum,
                                                  nx, nq, no);
    }

    // 1) qkvh = xh @ W_qkv^T   [16384 x 3072, K=1024] -> fp16  (NT)
    gemm_f16<1, true><<<dim3(3 * D_MODEL / TN, BS / TM, 1), 256, SMEM_TOTAL>>>(
        xh, wqkvh, qkvh, D_MODEL, D_MODEL, D_MODEL, 3 * D_MODEL, 0, 0, 0, 1.0f, nullptr);

    // 2) eh = exp(Q @ K^T / 32), rowsum += row sums  [4096 x 4096, K=1024] x4  (NT)
    gemm_f16<2, true><<<dim3(S_LEN / TN, S_LEN / TM, BATCH), 256, SMEM_TOTAL>>>(
        qkvh, qkvh + D_MODEL, eh, D_MODEL, 3 * D_MODEL, 3 * D_MODEL, S_LEN,
        qkv_bs, qkv_bs, log_bs, 0.03125f, rowsum);

    // 3) attnh = (eh @ V) / rowsum   [4096 x 1024, K=4096] x4 -> fp16  (NN, V in-place)
    gemm_f16<3, false><<<dim3(D_MODEL / TN, S_LEN / TM, BATCH), 256, SMEM_TOTAL>>>(
        eh, qkvh + 2 * D_MODEL, attnh, S_LEN, S_LEN, 3 * D_MODEL, D_MODEL,
        log_bs, qkv_bs, att_bs, 1.0f, rowsum);

    // 4) out = attnh @ W_o^T   [16384 x 1024, K=1024] -> fp32  (NT)
    gemm_f16<0, true><<<dim3(D_MODEL / TN, BS / TM, 1), 256, SMEM_TOTAL>>>(
        attnh, woh, out, D_MODEL, D_MODEL, D_MODEL, D_MODEL, 0, 0, 0, 1.0f, nullptr);
}

// round 17
// speedup vs baseline: 1.0021x; 1.0021x over previous
#include <cuda_runtime.h>
#include <cuda_fp16.h>
#include <cstdint>

#define BATCH 4
#define S_LEN 4096
#define D_MODEL 1024

// ---------------- scratch (module-load device globals) ----------------
__device__ __half g_eh[(size_t)BATCH * S_LEN * S_LEN];                  // fp16 exp(logits)
__device__ float  g_rowsum[(size_t)BATCH * S_LEN];                      // fp32 row sums
__device__ __half g_qkvh[(size_t)BATCH * S_LEN * 3 * D_MODEL];          // fp16 [B,S,3D]
__device__ __half g_xh[(size_t)BATCH * S_LEN * D_MODEL];                // fp16 x
__device__ __half g_wqkvh[(size_t)3 * D_MODEL * D_MODEL];               // fp16 W_qkv
__device__ __half g_woh[(size_t)D_MODEL * D_MODEL];                     // fp16 W_o
__device__ __half g_attnh[(size_t)BATCH * S_LEN * D_MODEL];             // fp16 attn

// ---------------- helpers ----------------
__device__ __forceinline__ uint32_t smem_u32(const void* p) {
    uint32_t a;
    asm("{ .reg .u64 t; cvta.to.shared.u64 t, %1; cvt.u32.u64 %0, t; }" : "=r"(a) : "l"(p));
    return a;
}
__device__ __forceinline__ void cp16(uint32_t dst, const void* src) {
    asm volatile("cp.async.cg.shared.global [%0], [%1], 16;" :: "r"(dst), "l"(src));
}
__device__ __forceinline__ void ldsm_x4(uint32_t* r, uint32_t addr) {
    asm volatile("ldmatrix.sync.aligned.m8n8.x4.shared.b16 {%0,%1,%2,%3}, [%4];"
                 : "=r"(r[0]), "=r"(r[1]), "=r"(r[2]), "=r"(r[3]) : "r"(addr));
}
__device__ __forceinline__ void ldsm_x4_t(uint32_t* r, uint32_t addr) {
    asm volatile("ldmatrix.sync.aligned.m8n8.x4.trans.shared.b16 {%0,%1,%2,%3}, [%4];"
                 : "=r"(r[0]), "=r"(r[1]), "=r"(r[2]), "=r"(r[3]) : "r"(addr));
}
__device__ __forceinline__ void mma16816(float* c,
                                         uint32_t a0, uint32_t a1, uint32_t a2, uint32_t a3,
                                         uint32_t b0, uint32_t b1) {
    asm volatile(
        "mma.sync.aligned.m16n8k16.row.col.f32.f16.f16.f32 "
        "{%0,%1,%2,%3}, {%4,%5,%6,%7}, {%8,%9}, {%0,%1,%2,%3};"
        : "+f"(c[0]), "+f"(c[1]), "+f"(c[2]), "+f"(c[3])
        : "r"(a0), "r"(a1), "r"(a2), "r"(a3), "r"(b0), "r"(b1));
}

// ---------------- fp16 GEMM ----------------
// BT=true : C[M,N] = f(A[M,K] @ B[N,K]^T)   (NT, both K-major)
// BT=false: C[M,N] = f(A[M,K] @ B[K,N])     (NN, B row-major [K,N], ldmatrix.trans)
// MODE: 0 = fp32 C (*alpha), 1 = fp16 C (*alpha),
//       2 = fp16 C = exp(acc*alpha) + fp32 rowsum atomics, 3 = fp16 C = acc / rowsum[row].
#define TM 128
#define TN 128
#define TBK 64
#define A_BYTES (TM * TBK * 2)            // 16384
#define STAGE_BYTES ((TM + TN) * TBK * 2) // 32768
#define NSTAGE 3
#define SMEM_TOTAL (NSTAGE * STAGE_BYTES) // 98304

template<int MODE, bool BT>
__global__ void __launch_bounds__(256, 2)
gemm_f16(const __half* __restrict__ A, const __half* __restrict__ B, void* __restrict__ Cv,
         int Kd, int lda, int ldb, int ldc,
         size_t sA, size_t sB, size_t sC, float alpha, float* __restrict__ rs)
{
    extern __shared__ char smem[];
    const uint32_t sb = smem_u32(smem);
    const int tid  = threadIdx.x;
    const int warp = tid >> 5, lane = tid & 31;
    const int wm = (warp & 3) * 32;       // 4 warps along M
    const int wn = (warp >> 2) * 64;      // 2 warps along N

    const int cta_m = blockIdx.y * TM;
    const int cta_n = blockIdx.x * TN;
    const __half* Ab = A + sA * blockIdx.z + (size_t)cta_m * lda;
    const __half* Bb = BT ? (B + sB * blockIdx.z + (size_t)cta_n * ldb)
                          : (B + sB * blockIdx.z + cta_n);

    // ---- cp.async loader geometry ----
    const int ld_row = tid >> 3;          // A: 0..31 (stepped by +32)
    const int ld_s   = tid & 7;
    const uint32_t ld_sw = (uint32_t)((ld_s ^ (ld_row & 7)) << 4);

    const char* a_src[4];
    uint32_t a_dst[4];
    #pragma unroll
    for (int p = 0; p < 4; p++) {
        int r = ld_row + p * 32;
        a_src[p] = (const char*)(Ab + (size_t)r * lda) + ld_s * 16;
        a_dst[p] = (uint32_t)(r * 128) + ld_sw;
    }

    const char* b_src[4];
    uint32_t b_dst[4];
    if (BT) {
        #pragma unroll
        for (int p = 0; p < 4; p++) {
            int r = ld_row + p * 32;
            b_src[p] = (const char*)(Bb + (size_t)r * ldb) + ld_s * 16;
            b_dst[p] = (uint32_t)(r * 128) + ld_sw + A_BYTES;
        }
    } else {
        // B tile [64 k-rows x 128 n] = 256B/row, 16 chunks; c' = c ^ (r&7)
        const int rr = tid >> 4;          // 0..15 (stepped by +16)
        const int cc = tid & 15;
        #pragma unroll
        for (int p = 0; p < 4; p++) {
            int r = rr + p * 16;
            b_src[p] = (const char*)Bb + (size_t)r * ldb * 2 + cc * 16;
            b_dst[p] = (uint32_t)(r * 256 + ((cc ^ (r & 7)) << 4)) + A_BYTES;
        }
    }

    auto load_stage = [&](uint32_t stoff, int kt) {
        const uint32_t base = sb + stoff;
        const size_t koff_a = (size_t)kt * TBK * 2;
        const size_t koff_b = BT ? koff_a : (size_t)kt * TBK * ldb * 2;
        #pragma unroll
        for (int p = 0; p < 4; p++) cp16(base + a_dst[p], a_src[p] + koff_a);
        #pragma unroll
        for (int p = 0; p < 4; p++) cp16(base + b_dst[p], b_src[p] + koff_b);
        asm volatile("cp.async.commit_group;" ::: "memory");
    };

    float acc[2][8][4];
    #pragma unroll
    for (int i = 0; i < 2; i++)
        #pragma unroll
        for (int j = 0; j < 8; j++)
            #pragma unroll
            for (int k = 0; k < 4; k++) acc[i][j][k] = 0.f;

    const int KT = Kd / TBK;
    load_stage(0, 0);
    if (KT > 1) load_stage(STAGE_BYTES, 1);
    else        asm volatile("cp.async.commit_group;" ::: "memory");

    // ---- fragment-load geometry ----
    const int l15 = lane & 15, l7 = lane & 7, lhi = lane >> 4;
    uint32_t swk[4];
    #pragma unroll
    for (int ks = 0; ks < 4; ks++) swk[ks] = (uint32_t)(((ks * 2 + lhi) ^ l7) << 4);
    const uint32_t arow_off = (uint32_t)((wm + l15) * 128);
    const uint32_t brow_off = (uint32_t)((wn + l15) * 128) + A_BYTES;
    // NN B path (ldmatrix.trans): lane row = kgrp*8 + (l&7); chunk = nseg ^ (l&7)
    const int bn0 = wn >> 3;
    const uint32_t bt_row = (uint32_t)(((lhi & 1) * 8 + l7) * 256) + A_BYTES;
    uint32_t bt_chunk[4];
    #pragma unroll
    for (int j = 0; j < 4; j++)
        bt_chunk[j] = (uint32_t)(((bn0 + 2 * j + ((lane >> 3) & 1)) ^ l7) << 4);

    uint32_t cur_off = 0;
    uint32_t pre_off = 2 * STAGE_BYTES;

    for (int kt = 0; kt < KT; kt++) {
        asm volatile("cp.async.wait_group 1;" ::: "memory");
        __syncthreads();
        if (kt + 2 < KT) load_stage(pre_off, kt + 2);

        const uint32_t arow = sb + cur_off + arow_off;

        uint32_t af[2][2][4], bf[2][4][4];
        // preload ks=0 fragments
        #pragma unroll
        for (int mt = 0; mt < 2; mt++) ldsm_x4(af[0][mt], arow + mt * 2048 + swk[0]);
        if (BT) {
            const uint32_t brow = sb + cur_off + brow_off;
            #pragma unroll
            for (int j = 0; j < 4; j++) ldsm_x4(bf[0][j], brow + j * 2048 + swk[0]);
        } else {
            const uint32_t bbase = sb + cur_off + bt_row;
            #pragma unroll
            for (int j = 0; j < 4; j++) ldsm_x4_t(bf[0][j], bbase + bt_chunk[j]);
        }

        #pragma unroll
        for (int ks = 0; ks < 4; ks++) {
            const int c = ks & 1, n = c ^ 1;
            if (ks < 3) {
                #pragma unroll
                for (int mt = 0; mt < 2; mt++) ldsm_x4(af[n][mt], arow + mt * 2048 + swk[ks + 1]);
                if (BT) {
                    const uint32_t brow = sb + cur_off + brow_off;
                    #pragma unroll
                    for (int j = 0; j < 4; j++) ldsm_x4(bf[n][j], brow + j * 2048 + swk[ks + 1]);
                } else {
                    const uint32_t bbase = sb + cur_off + bt_row + (uint32_t)(ks + 1) * 4096;
                    #pragma unroll
                    for (int j = 0; j < 4; j++) ldsm_x4_t(bf[n][j], bbase + bt_chunk[j]);
                }
            }
            #pragma unroll
            for (int mt = 0; mt < 2; mt++)
                #pragma unroll
                for (int nt = 0; nt < 8; nt++)
                    mma16816(acc[mt][nt],
                             af[c][mt][0], af[c][mt][1], af[c][mt][2], af[c][mt][3],
                             bf[c][nt >> 1][nt & 1], bf[c][nt >> 1][(nt & 1) + 2]);
        }

        uint32_t t = cur_off;
        cur_off = (cur_off == 2 * STAGE_BYTES) ? 0u : cur_off + STAGE_BYTES;
        pre_off = t;
    }

    // ---------------- epilogue ----------------
    const int er = lane >> 2, ec = (lane & 3) * 2;

    if (MODE == 2) {
        __half* C = (__half*)Cv + sC * blockIdx.z;
        float* rsb = rs + (size_t)blockIdx.z * S_LEN + cta_m;
        #pragma unroll
        for (int mt = 0; mt < 2; mt++) {
            const int r0 = wm + mt * 16 + er;
            float s0 = 0.f, s1 = 0.f;
            #pragma unroll
            for (int nt = 0; nt < 8; nt++) {
                const int col = cta_n + wn + nt * 8 + ec;
                float e0 = __expf(acc[mt][nt][0] * alpha);
                float e1 = __expf(acc[mt][nt][1] * alpha);
                float e2 = __expf(acc[mt][nt][2] * alpha);
                float e3 = __expf(acc[mt][nt][3] * alpha);
                s0 += e0 + e1;
                s1 += e2 + e3;
                *(__half2*)&C[(size_t)(cta_m + r0) * ldc + col]     = __floats2half2_rn(e0, e1);
                *(__half2*)&C[(size_t)(cta_m + r0 + 8) * ldc + col] = __floats2half2_rn(e2, e3);
            }
            s0 += __shfl_xor_sync(0xffffffffu, s0, 1);
            s0 += __shfl_xor_sync(0xffffffffu, s0, 2);
            s1 += __shfl_xor_sync(0xffffffffu, s1, 1);
            s1 += __shfl_xor_sync(0xffffffffu, s1, 2);
            if ((lane & 3) == 0) {
                atomicAdd(&rsb[r0],     s0);
                atomicAdd(&rsb[r0 + 8], s1);
            }
        }
    } else if (MODE == 3) {
        __half* C = (__half*)Cv + sC * blockIdx.z;
        const float* rsb = rs + (size_t)blockIdx.z * S_LEN + cta_m;
        #pragma unroll
        for (int mt = 0; mt < 2; mt++) {
            const int r0 = wm + mt * 16 + er;
            const float inv0 = 1.0f / rsb[r0];
            const float inv1 = 1.0f / rsb[r0 + 8];
            #pragma unroll
            for (int nt = 0; nt < 8; nt++) {
                const int col = cta_n + wn + nt * 8 + ec;
                *(__half2*)&C[(size_t)(cta_m + r0) * ldc + col] =
                    __floats2half2_rn(acc[mt][nt][0] * inv0, acc[mt][nt][1] * inv0);
                *(__half2*)&C[(size_t)(cta_m + r0 + 8) * ldc + col] =
                    __floats2half2_rn(acc[mt][nt][2] * inv1, acc[mt][nt][3] * inv1);
            }
        }
    } else {
        #pragma unroll
        for (int mt = 0; mt < 2; mt++) {
            const int row0 = cta_m + wm + mt * 16 + er;
            #pragma unroll
            for (int nt = 0; nt < 8; nt++) {
                const int col = cta_n + wn + nt * 8 + ec;
                if (MODE == 1) {
                    __half* C = (__half*)Cv + sC * blockIdx.z;
                    *(__half2*)&C[(size_t)row0 * ldc + col] =
                        __floats2half2_rn(acc[mt][nt][0] * alpha, acc[mt][nt][1] * alpha);
                    *(__half2*)&C[(size_t)(row0 + 8) * ldc + col] =
                        __floats2half2_rn(acc[mt][nt][2] * alpha, acc[mt][nt][3] * alpha);
                } else {
                    float* C = (float*)Cv + sC * blockIdx.z;
                    *(float2*)&C[(size_t)row0 * ldc + col] =
                        make_float2(acc[mt][nt][0] * alpha, acc[mt][nt][1] * alpha);
                    *(float2*)&C[(size_t)(row0 + 8) * ldc + col] =
                        make_float2(acc[mt][nt][2] * alpha, acc[mt][nt][3] * alpha);
                }
            }
        }
    }
}

// ---------------- prep: all fp32->fp16 converts + rowsum zero, one launch --------
__global__ void prep(const float* __restrict__ x, const float* __restrict__ wq,
                     const float* __restrict__ wo,
                     __half* __restrict__ xh, __half* __restrict__ wqh,
                     __half* __restrict__ woh, float* __restrict__ rowsum,
                     int nx, int nq, int no)
{
    int i = blockIdx.x * blockDim.x + threadIdx.x;
    if (i < (BATCH * S_LEN) / 4)
        ((float4*)rowsum)[i] = make_float4(0.f, 0.f, 0.f, 0.f);

    const float* src; __half* dst; int j = i;
    if (j < nx)            { src = x;  dst = xh;  }
    else { j -= nx;
        if (j < nq)        { src = wq; dst = wqh; }
        else { j -= nq;
            if (j >= no) return;
            src = wo; dst = woh;
        }
    }
    float4 v = ((const float4*)src)[j];
    __half2 h0 = __floats2half2_rn(v.x, v.y);
    __half2 h1 = __floats2half2_rn(v.z, v.w);
    ((uint2*)dst)[j] = make_uint2(*(uint32_t*)&h0, *(uint32_t*)&h1);
}

// ---------------- launch ----------------
extern "C" void kernel_launch(void* const* d_in, const int* in_sizes, int n_in,
                              void* d_out, int out_size)
{
    const float* x    = (const float*)d_in[0];
    const float* wqkv = (const float*)d_in[1];
    const float* wo   = (const float*)d_in[2];
    float* out        = (float*)d_out;

    __half *eh, *qkvh, *xh, *wqkvh, *woh, *attnh;
    float* rowsum;
    cudaGetSymbolAddress((void**)&eh,     g_eh);
    cudaGetSymbolAddress((void**)&rowsum, g_rowsum);
    cudaGetSymbolAddress((void**)&qkvh,   g_qkvh);
    cudaGetSymbolAddress((void**)&xh,     g_xh);
    cudaGetSymbolAddress((void**)&wqkvh,  g_wqkvh);
    cudaGetSymbolAddress((void**)&woh,    g_woh);
    cudaGetSymbolAddress((void**)&attnh,  g_attnh);

    cudaFuncSetAttribute((const void*)gemm_f16<0, true>,  cudaFuncAttributeMaxDynamicSharedMemorySize, SMEM_TOTAL);
    cudaFuncSetAttribute((const void*)gemm_f16<1, true>,  cudaFuncAttributeMaxDynamicSharedMemorySize, SMEM_TOTAL);
    cudaFuncSetAttribute((const void*)gemm_f16<2, true>,  cudaFuncAttributeMaxDynamicSharedMemorySize, SMEM_TOTAL);
    cudaFuncSetAttribute((const void*)gemm_f16<3, false>, cudaFuncAttributeMaxDynamicSharedMemorySize, SMEM_TOTAL);

    const int BS = BATCH * S_LEN;                      // 16384
    const size_t qkv_bs = (size_t)S_LEN * 3 * D_MODEL;
    const size_t log_bs = (size_t)S_LEN * S_LEN;
    const size_t att_bs = (size_t)S_LEN * D_MODEL;

    // 0) converts + rowsum zero in one launch
    {
        int nx = BS * D_MODEL / 4;
        int nq = 3 * D_MODEL * D_MODEL / 4;
        int no = D_MODEL * D_MODEL / 4;
        prep<<<(nx + nq + no + 255) / 256, 256>>>(x, wqkv, wo, xh, wqkvh, woh, rowsum,
                                                  nx, nq, no);
    }

    // 1) qkvh = xh @ W_qkv^T   [16384 x 3072, K=1024] -> fp16  (NT)
    gemm_f16<1, true><<<dim3(3 * D_MODEL / TN, BS / TM, 1), 256, SMEM_TOTAL>>>(
        xh, wqkvh, qkvh, D_MODEL, D_MODEL, D_MODEL, 3 * D_MODEL, 0, 0, 0, 1.0f, nullptr);

    // 2) eh = exp(Q @ K^T / 32), rowsum += row sums  [4096 x 4096, K=1024] x4  (NT)
    gemm_f16<2, true><<<dim3(S_LEN / TN, S_LEN / TM, BATCH), 256, SMEM_TOTAL>>>(
        qkvh, qkvh + D_MODEL, eh, D_MODEL, 3 * D_MODEL, 3 * D_MODEL, S_LEN,
        qkv_bs, qkv_bs, log_bs, 0.03125f, rowsum);

    // 3) attnh = (eh @ V) / rowsum   [4096 x 1024, K=4096] x4 -> fp16  (NN, V in-place)
    gemm_f16<3, false><<<dim3(D_MODEL / TN, S_LEN / TM, BATCH), 256, SMEM_TOTAL>>>(
        eh, qkvh + 2 * D_MODEL, attnh, S_LEN, S_LEN, 3 * D_MODEL, D_MODEL,
        log_bs, qkv_bs, att_bs, 1.0f, rowsum);

    // 4) out = attnh @ W_o^T   [16384 x 1024, K=1024] -> fp32  (NT)
    gemm_f16<0, true><<<dim3(D_MODEL / TN, BS / TM, 1), 256, SMEM_TOTAL>>>(
        attnh, woh, out, D_MODEL, D_MODEL, D_MODEL, D_MODEL, 0, 0, 0, 1.0f, nullptr);
}